// round 3
// baseline (speedup 1.0000x reference)
#include <cuda_runtime.h>
#include <cuda_bf16.h>

#define NB 8
#define NT 16384
#define NH 512
#define NC 24
#define NK 100
#define FULL 0xffffffffu

// Scratch (device globals; no allocation allowed)
__device__ float g_scores[NB * NC * NT];        // [b][c][t]
__device__ float g_cum[NB * NC * (NT + 1)];     // [b][c][t], cum[0]=0

// ---------------------------------------------------------------------------
// Kernel 1: scores[b,t,c] = hidden[b,t,:] @ W[:,c] + bias[c], written [b][c][t]
// 256 threads/block, one row per thread, W staged in smem in two 256-row halves.
// ---------------------------------------------------------------------------
__global__ __launch_bounds__(256) void gemm_kernel(const float* __restrict__ hs,
                                                   const float* __restrict__ W,
                                                   const float* __restrict__ bias) {
    __shared__ __align__(16) float Wsm[256 * NC];   // 24 KB
    __shared__ float bsm[NC];
    const int tid = threadIdx.x;
    const int row = blockIdx.x * 256 + tid;         // row = b*NT + t
    if (tid < NC) bsm[tid] = bias[tid];

    float acc[NC];
#pragma unroll
    for (int c = 0; c < NC; ++c) acc[c] = 0.f;

    const float* hp = hs + (size_t)row * NH;

    for (int half = 0; half < 2; ++half) {
        __syncthreads();
        for (int i = tid; i < 256 * NC; i += 256) Wsm[i] = W[half * 256 * NC + i];
        __syncthreads();
        const float* hph = hp + half * 256;
        for (int h = 0; h < 256; h += 4) {
            float4 x = *(const float4*)(hph + h);
#pragma unroll
            for (int j = 0; j < 4; ++j) {
                const float a = (&x.x)[j];
                const float4* wr = (const float4*)(&Wsm[(h + j) * NC]);
#pragma unroll
                for (int q = 0; q < 6; ++q) {
                    float4 wv = wr[q];
                    acc[q * 4 + 0] = fmaf(a, wv.x, acc[q * 4 + 0]);
                    acc[q * 4 + 1] = fmaf(a, wv.y, acc[q * 4 + 1]);
                    acc[q * 4 + 2] = fmaf(a, wv.z, acc[q * 4 + 2]);
                    acc[q * 4 + 3] = fmaf(a, wv.w, acc[q * 4 + 3]);
                }
            }
        }
    }

    const int b = row / NT;
    const int t = row % NT;
#pragma unroll
    for (int c = 0; c < NC; ++c)
        g_scores[((size_t)(b * NC + c)) * NT + t] = acc[c] + bsm[c];
}

// ---------------------------------------------------------------------------
// Kernel 2: per-(b,c) inclusive prefix -> g_cum[b][c][1..T], g_cum[..][0]=0.
// One warp per (b,c). Coalesced thanks to [b][c][t] layout.
// ---------------------------------------------------------------------------
__global__ __launch_bounds__(32) void cumsum_kernel() {
    const int bc = blockIdx.x;                      // 0..191
    const int lane = threadIdx.x;
    const float* sp = g_scores + (size_t)bc * NT;
    float* cp = g_cum + (size_t)bc * (NT + 1);
    if (lane == 0) cp[0] = 0.f;
    float carry = 0.f;
#pragma unroll 2
    for (int base = 0; base < NT; base += 32) {
        float v = sp[base + lane];
#pragma unroll
        for (int off = 1; off < 32; off <<= 1) {
            float n = __shfl_up_sync(FULL, v, off);
            if (lane >= off) v += n;
        }
        cp[base + lane + 1] = carry + v;
        carry += __shfl_sync(FULL, v, 31);
    }
}

// ---------------------------------------------------------------------------
// Kernel 3: sequential semi-Markov scan. One CTA per batch, warp-per-channel.
// ring[c][s&127] = msg[s,c] - cum[s,c]; unwritten slots = -1e30 (masks s<0).
// alpha[t,c] = cum[t,c] + LSE_k( ring[t-k] + dur[k-1,c] ),  k=1..100
// msg[t,c]  = LSE_{c'}( alpha[t,c'] + trans[c',c] )
// out[b]    = LSE_c alpha[len,c]
// ---------------------------------------------------------------------------
__global__ __launch_bounds__(768) void scan_kernel(const float* __restrict__ trans,
                                                   const float* __restrict__ dur,
                                                   const int* __restrict__ lengths,
                                                   float* __restrict__ out) {
    __shared__ float ring[NC * 128];     // [c][slot]
    __shared__ float dsm[NC * NK];       // [c][k-1]  (transposed duration_bias)
    __shared__ float tsm[NC * NC];       // [c][c']   (transposed transition)
    __shared__ float alpha_sm[NC];

    const int tid = threadIdx.x;
    const int c = tid >> 5;
    const int lane = tid & 31;
    const int b = blockIdx.x;

    for (int i = tid; i < NC * 128; i += 768) ring[i] = ((i & 127) == 0) ? 0.f : -1e30f;
    for (int i = tid; i < NC * NK; i += 768) { int cc = i / NK, kk = i % NK; dsm[i] = dur[kk * NC + cc]; }
    for (int i = tid; i < NC * NC; i += 768) { int cc = i / NC, cp = i % NC; tsm[i] = trans[cp * NC + cc]; }
    __syncthreads();

    int len = lengths[b];
    len = len < 1 ? 1 : (len > NT ? NT : len);

    const float* cumb = g_cum + (size_t)(b * NC + c) * (NT + 1);
    float* ringc = ring + c * 128;
    const float d1 = dsm[c * NK + lane];                      // k = lane+1
    const float d2 = dsm[c * NK + lane + 32];                 // k = lane+33
    const float d3 = (lane < 4) ? 0.f : dsm[c * NK + lane + 60]; // placeholder unified below
    const float d3r = dsm[c * NK + ((lane + 64 < NK) ? lane + 64 : 0)]; // k = lane+65 (valid: lane+64<=95<100)
    const float d4 = (lane < 4) ? dsm[c * NK + lane + 96] : 0.f; // k = lane+97 (only lanes 0..3)
    const float tv = (lane < NC) ? tsm[c * NC + lane] : 0.f;
    (void)d3;

    for (int t0 = 1; t0 <= NT; t0 += 32) {
        const float cumreg = cumb[t0 + lane];
#pragma unroll 1
        for (int tt = 0; tt < 32; ++tt) {
            const int t = t0 + tt;
            const float cum_t = __shfl_sync(FULL, cumreg, tt);

            // -------- Phase A: window LSE over k --------
            const int base = t - 1 - lane;                    // s for k=lane+1
            float v1 = ringc[base & 127] + d1;
            float v2 = ringc[(base - 32) & 127] + d2;
            float v3 = ringc[(base - 64) & 127] + d3r;
            float v4 = (lane < 4) ? (ringc[(base - 96) & 127] + d4) : -1e30f;

            float vm = fmaxf(fmaxf(v1, v2), fmaxf(v3, v4));
#pragma unroll
            for (int off = 16; off > 0; off >>= 1)
                vm = fmaxf(vm, __shfl_xor_sync(FULL, vm, off));

            float e = __expf(v1 - vm) + __expf(v2 - vm) + __expf(v3 - vm) + __expf(v4 - vm);
#pragma unroll
            for (int off = 16; off > 0; off >>= 1)
                e += __shfl_xor_sync(FULL, e, off);

            const float alpha = cum_t + vm + __logf(e);
            if (lane == 0) alpha_sm[c] = alpha;
            __syncthreads();

            // -------- Phase B: cross-channel LSE through transition --------
            float av = (lane < NC) ? (alpha_sm[lane] + tv) : -1e30f;
            float am = av;
#pragma unroll
            for (int off = 16; off > 0; off >>= 1)
                am = fmaxf(am, __shfl_xor_sync(FULL, am, off));
            float e2 = __expf(av - am);
#pragma unroll
            for (int off = 16; off > 0; off >>= 1)
                e2 += __shfl_xor_sync(FULL, e2, off);
            const float msg = am + __logf(e2);
            if (lane == 0) ringc[t & 127] = msg - cum_t;

            // -------- Output at t == len --------
            if (t == len && c == 0) {
                float pv = (lane < NC) ? alpha_sm[lane] : -1e30f;
                float pm = pv;
#pragma unroll
                for (int off = 16; off > 0; off >>= 1)
                    pm = fmaxf(pm, __shfl_xor_sync(FULL, pm, off));
                float pe = __expf(pv - pm);
#pragma unroll
                for (int off = 16; off > 0; off >>= 1)
                    pe += __shfl_xor_sync(FULL, pe, off);
                if (lane == 0) out[b] = pm + __logf(pe);
            }
            __syncthreads();
        }
        if (t0 + 31 >= len) break;
    }
}

// ---------------------------------------------------------------------------
extern "C" void kernel_launch(void* const* d_in, const int* in_sizes, int n_in,
                              void* d_out, int out_size) {
    const float* hs    = (const float*)d_in[0];   // [B,T,H]
    const float* W     = (const float*)d_in[1];   // [H,C]
    const float* bias  = (const float*)d_in[2];   // [C]
    const float* trans = (const float*)d_in[3];   // [C,C]
    const float* dur   = (const float*)d_in[4];   // [K,C]
    const int*   len   = (const int*)d_in[5];     // [B]
    float* out = (float*)d_out;

    gemm_kernel<<<(NB * NT) / 256, 256>>>(hs, W, bias);
    cumsum_kernel<<<NB * NC, 32>>>();
    scan_kernel<<<NB, 768>>>(trans, dur, len, out);
}

// round 4
// speedup vs baseline: 1.3542x; 1.3542x over previous
#include <cuda_runtime.h>
#include <cuda_bf16.h>

#define NB 8
#define NT 16384
#define NH 512
#define NC 24
#define NK 100
#define FULL 0xffffffffu

// Scratch (device globals; no allocation allowed)
__device__ float g_scores[NB * NC * NT];        // [b][c][t]
__device__ float g_cum[NB * NC * (NT + 1)];     // [b][c][t], cum[0]=0

// ---------------------------------------------------------------------------
// Kernel 1: scores[b,t,c] = hidden[b,t,:] @ W[:,c] + bias[c], written [b][c][t]
// ---------------------------------------------------------------------------
__global__ __launch_bounds__(256) void gemm_kernel(const float* __restrict__ hs,
                                                   const float* __restrict__ W,
                                                   const float* __restrict__ bias) {
    __shared__ __align__(16) float Wsm[256 * NC];   // 24 KB
    __shared__ float bsm[NC];
    const int tid = threadIdx.x;
    const int row = blockIdx.x * 256 + tid;         // row = b*NT + t
    if (tid < NC) bsm[tid] = bias[tid];

    float acc[NC];
#pragma unroll
    for (int c = 0; c < NC; ++c) acc[c] = 0.f;

    const float* hp = hs + (size_t)row * NH;

    for (int half = 0; half < 2; ++half) {
        __syncthreads();
        for (int i = tid; i < 256 * NC; i += 256) Wsm[i] = W[half * 256 * NC + i];
        __syncthreads();
        const float* hph = hp + half * 256;
        for (int h = 0; h < 256; h += 4) {
            float4 x = *(const float4*)(hph + h);
#pragma unroll
            for (int j = 0; j < 4; ++j) {
                const float a = (&x.x)[j];
                const float4* wr = (const float4*)(&Wsm[(h + j) * NC]);
#pragma unroll
                for (int q = 0; q < 6; ++q) {
                    float4 wv = wr[q];
                    acc[q * 4 + 0] = fmaf(a, wv.x, acc[q * 4 + 0]);
                    acc[q * 4 + 1] = fmaf(a, wv.y, acc[q * 4 + 1]);
                    acc[q * 4 + 2] = fmaf(a, wv.z, acc[q * 4 + 2]);
                    acc[q * 4 + 3] = fmaf(a, wv.w, acc[q * 4 + 3]);
                }
            }
        }
    }

    const int b = row / NT;
    const int t = row % NT;
#pragma unroll
    for (int c = 0; c < NC; ++c)
        g_scores[((size_t)(b * NC + c)) * NT + t] = acc[c] + bsm[c];
}

// ---------------------------------------------------------------------------
// Kernel 2: per-(b,c) inclusive prefix -> g_cum[b][c][1..T], g_cum[..][0]=0.
// ---------------------------------------------------------------------------
__global__ __launch_bounds__(32) void cumsum_kernel() {
    const int bc = blockIdx.x;                      // 0..191
    const int lane = threadIdx.x;
    const float* sp = g_scores + (size_t)bc * NT;
    float* cp = g_cum + (size_t)bc * (NT + 1);
    if (lane == 0) cp[0] = 0.f;
    float carry = 0.f;
#pragma unroll 2
    for (int base = 0; base < NT; base += 32) {
        float v = sp[base + lane];
#pragma unroll
        for (int off = 1; off < 32; off <<= 1) {
            float n = __shfl_up_sync(FULL, v, off);
            if (lane >= off) v += n;
        }
        cp[base + lane + 1] = carry + v;
        carry += __shfl_sync(FULL, v, 31);
    }
}

// ---------------------------------------------------------------------------
// Kernel 3: exp-space sequential scan. One CTA per batch, warp-per-channel.
//
// Ring holds E[s,c] = exp(msg[s,c]-cum[s,c]) / 2^{S_c}. Each step:
//   D_c   = sum_k E[t-k,c]*exp(dur[k-1,c])            (dot product, no exps)
//   u_c   = D_c * exp(cum[t,c] + S_c*ln2 - m_B)       = exp(alpha[t,c]-m_B)
//   T_c   = sum_{c'} u_{c'} * exp(trans[c',c])
//   E_t,c = T_c * exp(-(cum[t,c]+S_c*ln2-m_B))        = exp(msg-cum)/2^{S_c}
// S_c absorbs E_t's binary exponent every step (exact pow-2 ring rescale).
// m_B: global shift, re-measured every 32 steps + linear extrapolation.
// partition at t=len: m_B + log(sum_c u_c).
// ---------------------------------------------------------------------------
__global__ __launch_bounds__(768) void scan_kernel(const float* __restrict__ trans,
                                                   const float* __restrict__ dur,
                                                   const int* __restrict__ lengths,
                                                   float* __restrict__ out) {
    __shared__ float ring[NC * 128];   // [c][slot], warp-private columns
    __shared__ float u_sm[2][NC];      // double-buffered alpha weights
    __shared__ float lvl[NC];          // per-channel level for m_B refresh
    __shared__ float mb_sm[2];         // {m0, mu}

    const int tid = threadIdx.x;
    const int c = tid >> 5;
    const int lane = tid & 31;
    const int b = blockIdx.x;
    const float LN2 = 0.6931471805599453f;

    for (int i = tid; i < NC * 128; i += 768) ring[i] = ((i & 127) == 0) ? 1.f : 0.f;

    // Per-lane constants: exp(duration_bias) mapped k = lane+1, +33, +65, +97.
    const float ed1 = __expf(dur[lane * NC + c]);
    const float ed2 = __expf(dur[(lane + 32) * NC + c]);
    const float ed3 = __expf(dur[(lane + 64) * NC + c]);
    const float ed4 = (lane < 4) ? __expf(dur[(lane + 96) * NC + c]) : 0.f;
    const float etr = (lane < NC) ? __expf(trans[lane * NC + c]) : 0.f;
    __syncthreads();

    int len = lengths[b];
    len = len < 1 ? 1 : (len > NT ? NT : len);

    const float* cumb = g_cum + (size_t)(b * NC + c) * (NT + 1);
    float* ringc = ring + c * 128;

    int   S = 0;          // integer log2 reference (exact)
    float g = 1.f;        // ring rescale factor for this step's reads (2^-de)
    float m0 = 0.f, mu = 0.f, m_prev = 0.f;

    for (int t0 = 1; t0 <= NT; t0 += 32) {
        if (t0 > 1) {
            // Refresh global shift m_B from channel levels (cum + S*ln2).
            if (lane == 0) lvl[c] = cumb[t0 - 1] + (float)S * LN2;
            __syncthreads();
            if (c == 0) {
                float v = (lane < NC) ? lvl[lane] : -3.0e38f;
#pragma unroll
                for (int off = 16; off > 0; off >>= 1)
                    v = fmaxf(v, __shfl_xor_sync(FULL, v, off));
                if (lane == 0) {
                    mb_sm[0] = v;
                    mb_sm[1] = (v - m_prev) * (1.f / 32.f);
                    m_prev = v;
                }
            }
            __syncthreads();
            m0 = mb_sm[0];
            mu = mb_sm[1];
        }
        const float cumreg = cumb[t0 + lane];
#pragma unroll 1
        for (int tt = 0; tt < 32; ++tt) {
            const int t = t0 + tt;
            const float cum_t = __shfl_sync(FULL, cumreg, tt);
            const float mB = fmaf(mu, (float)(tt + 1), m0);
            const float R = (float)S * LN2;

            // ---- Phase A: rescale ring + dot product with exp(dur) ----
            const int s1 = (t - 1 - lane) & 127;
            float E1 = ringc[s1] * g;
            float E2 = ringc[(s1 - 32) & 127] * g;
            float E3 = ringc[(s1 - 64) & 127] * g;
            float E4 = (lane < 4) ? ringc[(s1 - 96) & 127] * g : 0.f;
            ringc[s1] = E1;
            ringc[(s1 - 32) & 127] = E2;
            ringc[(s1 - 64) & 127] = E3;
            if (lane < 4) ringc[(s1 - 96) & 127] = E4;

            float d = fmaf(E1, ed1, fmaf(E2, ed2, fmaf(E3, ed3, E4 * ed4)));
#pragma unroll
            for (int off = 16; off > 0; off >>= 1)
                d += __shfl_xor_sync(FULL, d, off);

            float x = cum_t + R - mB;
            x = fminf(fmaxf(x, -80.f), 80.f);
            const float a  = __expf(x);
            const float ra = __expf(-x);
            const float u = d * a;
            const int par = t & 1;
            if (lane == 0) u_sm[par][c] = u;
            __syncthreads();

            // ---- Phase B: cross-channel weighted sum through exp(trans) ----
            const float uv = (lane < NC) ? u_sm[par][lane] : 0.f;
            if (t == len && c == 0) {
                float su = uv;
#pragma unroll
                for (int off = 16; off > 0; off >>= 1)
                    su += __shfl_xor_sync(FULL, su, off);
                if (lane == 0) out[b] = mB + __logf(su);
            }
            float w = uv * etr;
#pragma unroll
            for (int off = 16; off > 0; off >>= 1)
                w += __shfl_xor_sync(FULL, w, off);

            const float Et = w * ra;                 // exp(msg-cum)/2^S
            if (lane == 0) ringc[t & 127] = Et;

            // Exponent-normalize for next step (exact pow-2, pure ALU).
            int de = ((__float_as_int(Et) >> 23) & 255) - 127;
            de = de < -40 ? -40 : (de > 40 ? 40 : de);
            g = __int_as_float((127 - de) << 23);    // 2^{-de}
            S += de;
        }
        if (t0 + 31 >= len) break;
    }
}

// ---------------------------------------------------------------------------
extern "C" void kernel_launch(void* const* d_in, const int* in_sizes, int n_in,
                              void* d_out, int out_size) {
    const float* hs    = (const float*)d_in[0];   // [B,T,H]
    const float* W     = (const float*)d_in[1];   // [H,C]
    const float* bias  = (const float*)d_in[2];   // [C]
    const float* trans = (const float*)d_in[3];   // [C,C]
    const float* dur   = (const float*)d_in[4];   // [K,C]
    const int*   len   = (const int*)d_in[5];     // [B]
    float* out = (float*)d_out;

    gemm_kernel<<<(NB * NT) / 256, 256>>>(hs, W, bias);
    cumsum_kernel<<<NB * NC, 32>>>();
    scan_kernel<<<NB, 768>>>(trans, dur, len, out);
}

// round 10
// speedup vs baseline: 1.4961x; 1.1048x over previous
#include <cuda_runtime.h>
#include <cuda_bf16.h>

#define NB 8
#define NT 16384
#define NH 512
#define NC 24
#define NK 100
#define FULL 0xffffffffu

// Scratch (device globals; no allocation allowed)
__device__ float g_scores[NB * NC * NT];        // [b][c][t]
__device__ float g_cum[NB * NC * (NT + 1)];     // [b][c][t], cum[0]=0

// ---------------------------------------------------------------------------
// Kernel 1: scores[b,t,c] = hidden[b,t,:] @ W[:,c] + bias[c], written [b][c][t]
// ---------------------------------------------------------------------------
__global__ __launch_bounds__(256) void gemm_kernel(const float* __restrict__ hs,
                                                   const float* __restrict__ W,
                                                   const float* __restrict__ bias) {
    __shared__ __align__(16) float Wsm[256 * NC];   // 24 KB
    __shared__ float bsm[NC];
    const int tid = threadIdx.x;
    const int row = blockIdx.x * 256 + tid;         // row = b*NT + t
    if (tid < NC) bsm[tid] = bias[tid];

    float acc[NC];
#pragma unroll
    for (int c = 0; c < NC; ++c) acc[c] = 0.f;

    const float* hp = hs + (size_t)row * NH;

    for (int half = 0; half < 2; ++half) {
        __syncthreads();
        for (int i = tid; i < 256 * NC; i += 256) Wsm[i] = W[half * 256 * NC + i];
        __syncthreads();
        const float* hph = hp + half * 256;
        for (int h = 0; h < 256; h += 4) {
            float4 x = *(const float4*)(hph + h);
#pragma unroll
            for (int j = 0; j < 4; ++j) {
                const float a = (&x.x)[j];
                const float4* wr = (const float4*)(&Wsm[(h + j) * NC]);
#pragma unroll
                for (int q = 0; q < 6; ++q) {
                    float4 wv = wr[q];
                    acc[q * 4 + 0] = fmaf(a, wv.x, acc[q * 4 + 0]);
                    acc[q * 4 + 1] = fmaf(a, wv.y, acc[q * 4 + 1]);
                    acc[q * 4 + 2] = fmaf(a, wv.z, acc[q * 4 + 2]);
                    acc[q * 4 + 3] = fmaf(a, wv.w, acc[q * 4 + 3]);
                }
            }
        }
    }

    const int b = row / NT;
    const int t = row % NT;
#pragma unroll
    for (int c = 0; c < NC; ++c)
        g_scores[((size_t)(b * NC + c)) * NT + t] = acc[c] + bsm[c];
}

// ---------------------------------------------------------------------------
// Kernel 2: per-(b,c) inclusive prefix -> g_cum[b][c][1..T], g_cum[..][0]=0.
// ---------------------------------------------------------------------------
__global__ __launch_bounds__(32) void cumsum_kernel() {
    const int bc = blockIdx.x;                      // 0..191
    const int lane = threadIdx.x;
    const float* sp = g_scores + (size_t)bc * NT;
    float* cp = g_cum + (size_t)bc * (NT + 1);
    if (lane == 0) cp[0] = 0.f;
    float carry = 0.f;
#pragma unroll 2
    for (int base = 0; base < NT; base += 32) {
        float v = sp[base + lane];
#pragma unroll
        for (int off = 1; off < 32; off <<= 1) {
            float n = __shfl_up_sync(FULL, v, off);
            if (lane >= off) v += n;
        }
        cp[base + lane + 1] = carry + v;
        carry += __shfl_sync(FULL, v, 31);
    }
}

// ---------------------------------------------------------------------------
// Kernel 3: hybrid scan. One CTA per batch, warp-per-channel (24 warps).
//
// Phase A (exp space, pipelined): ring E[s,c]=exp(msg[s]-cum[s]-R_c).
//   Free-energy growth is ~3.7 nats/step, so the anchor R_c is advanced every
//   8 steps (warp-local, butterfly-free): scale so that E[t-1] -> 2^{-45}.
//   Hard bounds: per-step growth <= e^{8.9}; 8-step excursion from e^{-31}
//   stays <= e^{40} << e^{88}. Entries >e^{88} below max flush to 0, exactly
//   like fp32 LSE in the reference.
//   tail(t+1) = sum_{k>=2} E[t+1-k] ed[k] computed during step t; at step t:
//   D = E[t-1]*ed1 + tail;  alpha[t,c] = log(D) + cum[t,c] + R_c.
// Phase B (log domain, per-step max -- bounded):
//   av = alpha[c'] + trans[c',c];  am = max;  e2 = sum exp(av-am) (in [1,24]);
//   E[t] = e2 * exp(am - cum[t,c] - R_c).
// 3 MUFU per warp-step, 1 __syncthreads per step, interleaved butterflies.
// ---------------------------------------------------------------------------
__global__ __launch_bounds__(768) void scan_kernel(const float* __restrict__ trans,
                                                   const float* __restrict__ dur,
                                                   const int* __restrict__ lengths,
                                                   float* __restrict__ out) {
    __shared__ float ring[NC * 128];     // [c][slot]
    __shared__ float alpha_sm[2][NC];    // double-buffered

    const int tid = threadIdx.x;
    const int c = tid >> 5;
    const int lane = tid & 31;
    const int b = blockIdx.x;
    const float LN2 = 0.6931471805599453f;

    for (int i = tid; i < NC * 128; i += 768) ring[i] = ((i & 127) == 0) ? 1.f : 0.f;

    // Constants: ed1s = exp(dur[k=1]); lanes cover k = lane+2, +34, +66, +98.
    const float ed1s = __expf(dur[0 * NC + c]);
    const float edA = __expf(dur[(lane + 1) * NC + c]);    // k = lane+2
    const float edB = __expf(dur[(lane + 33) * NC + c]);   // k = lane+34
    const float edC = __expf(dur[(lane + 65) * NC + c]);   // k = lane+66
    const float edD = (lane < 3) ? __expf(dur[(lane + 97) * NC + c]) : 0.f; // k=98..100
    const float tv = (lane < NC) ? trans[lane * NC + c] : 0.f;
    __syncthreads();

    int len = lengths[b];
    len = len < 1 ? 1 : (len > NT ? NT : len);

    const float* cumb = g_cum + (size_t)(b * NC + c) * (NT + 1);
    float* ringc = ring + c * 128;

    float R = 0.f;                 // per-channel anchor ledger (pow-2 exact)
    float tailD = 0.f;             // sum_{k>=2} E[t-k]ed[k] for current t
    float Et1 = 1.f;               // E[t-1] (uniform across lanes)
    float cumNext = cumb[1 + lane];

    for (int t0 = 1; t0 <= NT; t0 += 32) {
        const float cumreg = cumNext;                        // lane -> cum[t0+lane]
        if (t0 + 32 <= NT) cumNext = cumb[t0 + 32 + lane];   // prefetch next block

#pragma unroll
        for (int grp = 0; grp < 4; ++grp) {
            if (t0 > 1 || grp > 0) {
                // ---- Warp-local re-anchor: Et1 -> ~2^{-45} (exact pow-2) ----
                int eb = (__float_as_int(Et1) >> 23) & 255;
                if (eb == 0) eb = 1;                 // Et1 denormal/zero guard
                int de = eb - 82;                    // Et1 * 2^{-de} ~= 2^{-45}
                de = de < -100 ? -100 : (de > 120 ? 120 : de);
                const float sc = __int_as_float((127 - de) << 23);   // 2^{-de}
                ringc[lane]      *= sc;
                ringc[lane + 32] *= sc;
                ringc[lane + 64] *= sc;
                ringc[lane + 96] *= sc;
                Et1 *= sc;
                tailD *= sc;
                R += (float)de * LN2;
            }
#pragma unroll 4
            for (int q = 0; q < 8; ++q) {
                const int tt = grp * 8 + q;
                const int t = t0 + tt;
                const float cr = __shfl_sync(FULL, cumreg, tt) + R;   // cum_t + R

                const float D = fmaf(Et1, ed1s, tailD);
                const float alpha = __logf(fmaxf(D, 1e-37f)) + cr;
                const int par = t & 1;
                if (lane == 0) alpha_sm[par][c] = alpha;
                __syncthreads();

                // Phase B (log-domain, per-step max).
                float av = (lane < NC) ? alpha_sm[par][lane] + tv : -3.0e38f;

                // Tail reads for step t+1 (warp-private ring); FMAs overlap
                // the max-butterfly's shfl latency.
                const float F1 = ringc[(t - 1 - lane) & 127];
                const float F2 = ringc[(t - 33 - lane) & 127];
                const float F3 = ringc[(t - 65 - lane) & 127];
                const float F4 = (lane < 3) ? ringc[(t - 97 - lane) & 127] : 0.f;

                float am = av;
#pragma unroll
                for (int off = 16; off > 0; off >>= 1)
                    am = fmaxf(am, __shfl_xor_sync(FULL, am, off));

                float tb = fmaf(F1, edA, fmaf(F2, edB, fmaf(F3, edC, F4 * edD)));
                float p = __expf(av - am);              // <= 1; lanes >= 24 -> 0

                // Two independent sum butterflies, interleaved for ILP.
#pragma unroll
                for (int off = 16; off > 0; off >>= 1) {
                    p  += __shfl_xor_sync(FULL, p, off);
                    tb += __shfl_xor_sync(FULL, tb, off);
                }

                const float Et = p * __expf(am - cr);
                if (lane == 0) ringc[t & 127] = Et;

                if (t == len && c == 0) {
                    float av0 = (lane < NC) ? alpha_sm[par][lane] : -3.0e38f;
                    float am0 = av0;
#pragma unroll
                    for (int off = 16; off > 0; off >>= 1)
                        am0 = fmaxf(am0, __shfl_xor_sync(FULL, am0, off));
                    float s0 = __expf(av0 - am0);
#pragma unroll
                    for (int off = 16; off > 0; off >>= 1)
                        s0 += __shfl_xor_sync(FULL, s0, off);
                    if (lane == 0) out[b] = am0 + __logf(s0);
                }

                Et1 = Et;
                tailD = tb;
            }
        }
        if (t0 + 31 >= len) break;
    }
}

// ---------------------------------------------------------------------------
extern "C" void kernel_launch(void* const* d_in, const int* in_sizes, int n_in,
                              void* d_out, int out_size) {
    const float* hs    = (const float*)d_in[0];   // [B,T,H]
    const float* W     = (const float*)d_in[1];   // [H,C]
    const float* bias  = (const float*)d_in[2];   // [C]
    const float* trans = (const float*)d_in[3];   // [C,C]
    const float* dur   = (const float*)d_in[4];   // [K,C]
    const int*   len   = (const int*)d_in[5];     // [B]
    float* out = (float*)d_out;

    gemm_kernel<<<(NB * NT) / 256, 256>>>(hs, W, bias);
    cumsum_kernel<<<NB * NC, 32>>>();
    scan_kernel<<<NB, 768>>>(trans, dur, len, out);
}

// round 11
// speedup vs baseline: 1.6322x; 1.0909x over previous
#include <cuda_runtime.h>
#include <cuda_bf16.h>

#define NB 8
#define NT 16384
#define NH 512
#define NC 24
#define NK 100
#define FULL 0xffffffffu

// Scratch (device globals; no allocation allowed)
__device__ float g_scores[NB * NC * NT];        // [b][c][t]
__device__ float g_cum[NB * NC * (NT + 1)];     // [b][c][t], cum[0]=0

// ---------------------------------------------------------------------------
// Kernel 1: scores[b,t,c] = hidden[b,t,:] @ W[:,c] + bias[c], written [b][c][t]
// ---------------------------------------------------------------------------
__global__ __launch_bounds__(256) void gemm_kernel(const float* __restrict__ hs,
                                                   const float* __restrict__ W,
                                                   const float* __restrict__ bias) {
    __shared__ __align__(16) float Wsm[256 * NC];   // 24 KB
    __shared__ float bsm[NC];
    const int tid = threadIdx.x;
    const int row = blockIdx.x * 256 + tid;         // row = b*NT + t
    if (tid < NC) bsm[tid] = bias[tid];

    float acc[NC];
#pragma unroll
    for (int c = 0; c < NC; ++c) acc[c] = 0.f;

    const float* hp = hs + (size_t)row * NH;

    for (int half = 0; half < 2; ++half) {
        __syncthreads();
        for (int i = tid; i < 256 * NC; i += 256) Wsm[i] = W[half * 256 * NC + i];
        __syncthreads();
        const float* hph = hp + half * 256;
        for (int h = 0; h < 256; h += 4) {
            float4 x = *(const float4*)(hph + h);
#pragma unroll
            for (int j = 0; j < 4; ++j) {
                const float a = (&x.x)[j];
                const float4* wr = (const float4*)(&Wsm[(h + j) * NC]);
#pragma unroll
                for (int q = 0; q < 6; ++q) {
                    float4 wv = wr[q];
                    acc[q * 4 + 0] = fmaf(a, wv.x, acc[q * 4 + 0]);
                    acc[q * 4 + 1] = fmaf(a, wv.y, acc[q * 4 + 1]);
                    acc[q * 4 + 2] = fmaf(a, wv.z, acc[q * 4 + 2]);
                    acc[q * 4 + 3] = fmaf(a, wv.w, acc[q * 4 + 3]);
                }
            }
        }
    }

    const int b = row / NT;
    const int t = row % NT;
#pragma unroll
    for (int c = 0; c < NC; ++c)
        g_scores[((size_t)(b * NC + c)) * NT + t] = acc[c] + bsm[c];
}

// ---------------------------------------------------------------------------
// Kernel 2: per-(b,c) inclusive prefix -> g_cum[b][c][1..T], g_cum[..][0]=0.
// ---------------------------------------------------------------------------
__global__ __launch_bounds__(32) void cumsum_kernel() {
    const int bc = blockIdx.x;                      // 0..191
    const int lane = threadIdx.x;
    const float* sp = g_scores + (size_t)bc * NT;
    float* cp = g_cum + (size_t)bc * (NT + 1);
    if (lane == 0) cp[0] = 0.f;
    float carry = 0.f;
#pragma unroll 2
    for (int base = 0; base < NT; base += 32) {
        float v = sp[base + lane];
#pragma unroll
        for (int off = 1; off < 32; off <<= 1) {
            float n = __shfl_up_sync(FULL, v, off);
            if (lane >= off) v += n;
        }
        cp[base + lane + 1] = carry + v;
        carry += __shfl_sync(FULL, v, 31);
    }
}

// ---------------------------------------------------------------------------
// Kernel 3: exp-space scan with feedback-tracked shift.
// One CTA per batch, warp-per-channel (24 warps).
//
// Ring: E[s,c] = exp(msg[s]-cum[s]-R_c); R_c advanced every 8 steps
// (warp-local, Et1 -> 2^{-45}, exact pow-2). Per step:
//   D   = E[t-1]*ed1 + tail            (tail pipelined from prior step)
//   u_c = D * beta,  beta = exp(cum+R-shift)  =>  u_c = exp(alpha_c - shift)
//   w_c = sum_{c'} u_{c'} * exp(trans[c',c])   (single sum butterfly)
//   E[t] = w * rbeta
//   shift += ilogb(u_0)*ln2            (pure ALU, uniform across warps)
// beta/rbeta recomputed per step via 2 exps OFF the critical chain, and
// corrected by exact pow-2 at each re-anchor. No log / max in the loop.
// ---------------------------------------------------------------------------
__global__ __launch_bounds__(768) void scan_kernel(const float* __restrict__ trans,
                                                   const float* __restrict__ dur,
                                                   const int* __restrict__ lengths,
                                                   float* __restrict__ out) {
    __shared__ float ring[NC * 128];     // [c][slot]
    __shared__ float u_sm[2][NC];        // double-buffered

    const int tid = threadIdx.x;
    const int c = tid >> 5;
    const int lane = tid & 31;
    const int b = blockIdx.x;
    const float LN2 = 0.6931471805599453f;

    for (int i = tid; i < NC * 128; i += 768) ring[i] = ((i & 127) == 0) ? 1.f : 0.f;

    // Constants: ed1s = exp(dur[k=1]); lanes cover k = lane+2, +34, +66, +98.
    const float ed1s = __expf(dur[0 * NC + c]);
    const float edA = __expf(dur[(lane + 1) * NC + c]);    // k = lane+2
    const float edB = __expf(dur[(lane + 33) * NC + c]);   // k = lane+34
    const float edC = __expf(dur[(lane + 65) * NC + c]);   // k = lane+66
    const float edD = (lane < 3) ? __expf(dur[(lane + 97) * NC + c]) : 0.f; // k=98..100
    const float etr = (lane < NC) ? __expf(trans[lane * NC + c]) : 0.f;
    __syncthreads();

    int len = lengths[b];
    len = len < 1 ? 1 : (len > NT ? NT : len);

    const float* cumb = g_cum + (size_t)(b * NC + c) * (NT + 1);
    float* ringc = ring + c * 128;

    float R = 0.f;                 // per-channel anchor ledger (pow-2 exact)
    float shift = 0.f;             // global scale tracker (uniform across warps)
    float tailD = 0.f;             // sum_{k>=2} E[t-k]ed[k] for current t
    float Et1 = 1.f;               // E[t-1] (uniform across lanes)
    float cumNext = cumb[1 + lane];

    // Initial beta/rbeta for t=1 (R=0, shift=0).
    float xb = __shfl_sync(FULL, cumNext, 0);
    float beta = __expf(xb);
    float rbeta = __expf(-xb);

    for (int t0 = 1; t0 <= NT; t0 += 32) {
        const float cumreg = cumNext;                        // lane -> cum[t0+lane]
        if (t0 + 32 <= NT) cumNext = cumb[t0 + 32 + lane];   // prefetch next block

#pragma unroll
        for (int grp = 0; grp < 4; ++grp) {
            if (t0 > 1 || grp > 0) {
                __syncwarp();
                // ---- Warp-local re-anchor: Et1 -> ~2^{-45} (exact pow-2) ----
                int eb = (__float_as_int(Et1) >> 23) & 255;
                if (eb == 0) eb = 1;
                int de = eb - 82;                    // Et1 * 2^{-de} ~= 2^{-45}
                de = de < -100 ? -100 : (de > 120 ? 120 : de);
                const float sc  = __int_as_float((127 - de) << 23);  // 2^{-de}
                const float rsc = __int_as_float((127 + de) << 23);  // 2^{+de}
                ringc[lane]      *= sc;
                ringc[lane + 32] *= sc;
                ringc[lane + 64] *= sc;
                ringc[lane + 96] *= sc;
                Et1 *= sc;
                tailD *= sc;
                R += (float)de * LN2;
                beta  *= rsc;      // beta = exp(cum+R-shift): R grew by de*ln2
                rbeta *= sc;
            }
#pragma unroll 4
            for (int q = 0; q < 8; ++q) {
                const int tt = grp * 8 + q;
                const int t = t0 + tt;
                const int par = t & 1;

                const float D = fmaf(Et1, ed1s, tailD);
                const float u = D * beta;            // exp(alpha_c - shift)
                if (lane == 0) u_sm[par][c] = u;
                __syncthreads();

                const float uv = (lane < NC) ? u_sm[par][lane] : 0.f;

                // Tail reads for step t+1 (warp-private ring).
                const float F1 = ringc[(t - 1 - lane) & 127];
                const float F2 = ringc[(t - 33 - lane) & 127];
                const float F3 = ringc[(t - 65 - lane) & 127];
                const float F4 = (lane < 3) ? ringc[(t - 97 - lane) & 127] : 0.f;

                float w = uv * etr;
                float tb = fmaf(F1, edA, fmaf(F2, edB, fmaf(F3, edC, F4 * edD)));

                // Two independent sum butterflies, interleaved for ILP.
#pragma unroll
                for (int off = 16; off > 0; off >>= 1) {
                    w  += __shfl_xor_sync(FULL, w, off);
                    tb += __shfl_xor_sync(FULL, tb, off);
                }

                const float Et = w * rbeta;          // E[t] = exp(msg-cum-R)
                if (lane == 0) ringc[t & 127] = Et;

                if (t == len && c == 0) {
                    float su = uv;
#pragma unroll
                    for (int off = 16; off > 0; off >>= 1)
                        su += __shfl_xor_sync(FULL, su, off);
                    if (lane == 0) out[b] = shift + __logf(fmaxf(su, 1e-37f));
                }

                // ---- shift feedback (pure ALU; uniform across warps) ----
                const float u0 = __shfl_sync(FULL, uv, 0);
                int e0 = (__float_as_int(u0) >> 23) & 255;
                int ds = (e0 == 0) ? -30 : (e0 - 127);
                ds = ds < -30 ? -30 : (ds > 30 ? 30 : ds);
                shift = fmaf((float)ds, LN2, shift);

                // beta/rbeta for step t+1 (off critical chain).
                const float srcv = (tt < 31) ? cumreg : cumNext;
                const int   sidx = (tt < 31) ? (tt + 1) : 0;
                const float crN = __shfl_sync(FULL, srcv, sidx) + R;
                const float xn = crN - shift;
                beta = __expf(xn);
                rbeta = __expf(-xn);

                Et1 = Et;
                tailD = tb;
            }
        }
        if (t0 + 31 >= len) break;
    }
}

// ---------------------------------------------------------------------------
extern "C" void kernel_launch(void* const* d_in, const int* in_sizes, int n_in,
                              void* d_out, int out_size) {
    const float* hs    = (const float*)d_in[0];   // [B,T,H]
    const float* W     = (const float*)d_in[1];   // [H,C]
    const float* bias  = (const float*)d_in[2];   // [C]
    const float* trans = (const float*)d_in[3];   // [C,C]
    const float* dur   = (const float*)d_in[4];   // [K,C]
    const int*   len   = (const int*)d_in[5];     // [B]
    float* out = (float*)d_out;

    gemm_kernel<<<(NB * NT) / 256, 256>>>(hs, W, bias);
    cumsum_kernel<<<NB * NC, 32>>>();
    scan_kernel<<<NB, 768>>>(trans, dur, len, out);
}

// round 12
// speedup vs baseline: 2.4124x; 1.4780x over previous
#include <cuda_runtime.h>
#include <cuda_bf16.h>

#define NB 8
#define NT 16384
#define NH 512
#define NC 24
#define NK 100
#define RST 264            // ring stride in floats (256 live + 8 pad)
#define FULL 0xffffffffu

// Scratch (device globals; no allocation allowed)
__device__ float g_scores[NB * NC * NT];        // [b][c][t]
__device__ float g_cum[NB * NC * (NT + 1)];     // [b][c][t], cum[0]=0

// ---------------------------------------------------------------------------
// Kernel 1: scores[b,t,c] = hidden[b,t,:] @ W[:,c] + bias[c], written [b][c][t]
// ---------------------------------------------------------------------------
__global__ __launch_bounds__(256) void gemm_kernel(const float* __restrict__ hs,
                                                   const float* __restrict__ W,
                                                   const float* __restrict__ bias) {
    __shared__ __align__(16) float Wsm[256 * NC];   // 24 KB
    __shared__ float bsm[NC];
    const int tid = threadIdx.x;
    const int row = blockIdx.x * 256 + tid;         // row = b*NT + t
    if (tid < NC) bsm[tid] = bias[tid];

    float acc[NC];
#pragma unroll
    for (int c = 0; c < NC; ++c) acc[c] = 0.f;

    const float* hp = hs + (size_t)row * NH;

    for (int half = 0; half < 2; ++half) {
        __syncthreads();
        for (int i = tid; i < 256 * NC; i += 256) Wsm[i] = W[half * 256 * NC + i];
        __syncthreads();
        const float* hph = hp + half * 256;
        for (int h = 0; h < 256; h += 4) {
            float4 x = *(const float4*)(hph + h);
#pragma unroll
            for (int j = 0; j < 4; ++j) {
                const float a = (&x.x)[j];
                const float4* wr = (const float4*)(&Wsm[(h + j) * NC]);
#pragma unroll
                for (int q = 0; q < 6; ++q) {
                    float4 wv = wr[q];
                    acc[q * 4 + 0] = fmaf(a, wv.x, acc[q * 4 + 0]);
                    acc[q * 4 + 1] = fmaf(a, wv.y, acc[q * 4 + 1]);
                    acc[q * 4 + 2] = fmaf(a, wv.z, acc[q * 4 + 2]);
                    acc[q * 4 + 3] = fmaf(a, wv.w, acc[q * 4 + 3]);
                }
            }
        }
    }

    const int b = row / NT;
    const int t = row % NT;
#pragma unroll
    for (int c = 0; c < NC; ++c)
        g_scores[((size_t)(b * NC + c)) * NT + t] = acc[c] + bsm[c];
}

// ---------------------------------------------------------------------------
// Kernel 2: per-(b,c) inclusive prefix -> g_cum[b][c][1..T], g_cum[..][0]=0.
// ---------------------------------------------------------------------------
__global__ __launch_bounds__(32) void cumsum_kernel() {
    const int bc = blockIdx.x;                      // 0..191
    const int lane = threadIdx.x;
    const float* sp = g_scores + (size_t)bc * NT;
    float* cp = g_cum + (size_t)bc * (NT + 1);
    if (lane == 0) cp[0] = 0.f;
    float carry = 0.f;
#pragma unroll 2
    for (int base = 0; base < NT; base += 32) {
        float v = sp[base + lane];
#pragma unroll
        for (int off = 1; off < 32; off <<= 1) {
            float n = __shfl_up_sync(FULL, v, off);
            if (lane >= off) v += n;
        }
        cp[base + lane + 1] = carry + v;
        carry += __shfl_sync(FULL, v, 31);
    }
}

// ---------------------------------------------------------------------------
// Kernel 3: 6-warp scan. 4 channels/warp, 8 lanes/channel (group).
//
// Ring: double-written (slot t&127 and +128) so each lane's 13 window terms
// (k = 2+13*sl .. 2+13*sl+12, consecutive) are contiguous LDS with immediate
// offsets. Stride 264 floats -> conflict-free across all 32 lanes.
// Per step:  D = E[t-1]*ed1 + tail  (tail pipelined from prior step)
//            u_c = D*beta (beta=exp(cum+R-shift), computed prior step)
//            w_c = sum_{c'} u_{c'} e^{trans}  (3 FMA + 3-round group butterfly)
//            E[t] = w*rbeta ; tail_{t+1}: 13 LDS+FMA + 3-round butterfly
// R_c re-anchored every 8 steps (exact pow-2, E[t-1]->2^-45, warp-local).
// shift: per-step ALU feedback from u_0 (uniform). 2 MUFU/warp-step, off-chain.
// ---------------------------------------------------------------------------
__global__ __launch_bounds__(192) void scan_kernel(const float* __restrict__ trans,
                                                   const float* __restrict__ dur,
                                                   const int* __restrict__ lengths,
                                                   float* __restrict__ out) {
    __shared__ float ring[NC * RST];   // ~25.3 KB
    __shared__ float u_sm[2][NC];

    const int tid = threadIdx.x;
    const int warp = tid >> 5;
    const int lane = tid & 31;
    const int grp = lane >> 3;         // channel group within warp (0..3)
    const int sl = lane & 7;           // sub-lane within group
    const int c = warp * 4 + grp;      // this lane's channel
    const int laneBase = lane & 24;    // grp*8
    const int b = blockIdx.x;
    const float LN2 = 0.6931471805599453f;

    for (int i = tid; i < NC * RST; i += 192) {
        const int x = i % RST;
        ring[i] = (x == 0 || x == 128) ? 1.f : 0.f;
    }

    // Constants.
    const float ed1s = __expf(dur[0 * NC + c]);          // k = 1
    float edt[13];
#pragma unroll
    for (int i = 0; i < 13; ++i) {
        const int k = 2 + 13 * sl + i;
        edt[i] = (k <= NK) ? __expf(dur[(k - 1) * NC + c]) : 0.f;
    }
    const float etr0 = __expf(trans[(3 * sl + 0) * NC + c]);
    const float etr1 = __expf(trans[(3 * sl + 1) * NC + c]);
    const float etr2 = __expf(trans[(3 * sl + 2) * NC + c]);
    __syncthreads();

    int len = lengths[b];
    len = len < 1 ? 1 : (len > NT ? NT : len);

    const float* cumb = g_cum + (size_t)(b * NC + c) * (NT + 1);
    float* ringc = ring + c * RST;

    float R = 0.f, shift = 0.f, tailD = 0.f, Et1 = 1.f;

    // Block cum registers: cumA[m] = cum[c][(t0+1) + 8m + sl]  (covers t0+1..t0+32)
    float cumA[4], cumB[4];
#pragma unroll
    for (int m = 0; m < 4; ++m) cumA[m] = cumb[2 + 8 * m + sl];

    // beta for t=1: exp(cum[1] + R - shift) = exp(cum[1])
    {
        const float xb = cumb[1];
        float xc = fminf(fmaxf(xb, -80.f), 80.f);
        ; // (cum[1] is O(sqrt(H)) scale-free; no clamp issues in practice)
        (void)xc;
    }
    float beta = __expf(cumb[1]);
    float rbeta = __expf(-cumb[1]);

    for (int t0 = 1; t0 <= NT; t0 += 32) {
        // Prefetch next block's cum (clamped indices; unused past len/NT).
        if (t0 + 32 <= NT) {
#pragma unroll
            for (int m = 0; m < 4; ++m) {
                int idx = t0 + 33 + 8 * m + sl;
                idx = idx > NT ? NT : idx;
                cumB[m] = cumb[idx];
            }
        }

#pragma unroll
        for (int grp8 = 0; grp8 < 4; ++grp8) {
            if (t0 > 1 || grp8 > 0) {
                __syncwarp();
                // ---- group-local re-anchor: Et1 -> ~2^{-45} (exact pow-2) ----
                int eb = (__float_as_int(Et1) >> 23) & 255;
                if (eb == 0) eb = 1;
                int de = eb - 82;
                de = de < -100 ? -100 : (de > 120 ? 120 : de);
                const float sc = __int_as_float((127 - de) << 23);   // 2^{-de}
                const float rsc = __int_as_float((127 + de) << 23);  // 2^{+de}
#pragma unroll
                for (int m = 0; m < 32; ++m) ringc[sl + 8 * m] *= sc;
                Et1 *= sc;
                tailD *= sc;
                R += (float)de * LN2;
                beta *= rsc;
                rbeta *= sc;
            }
#pragma unroll
            for (int q = 0; q < 8; ++q) {
                const int tt = grp8 * 8 + q;
                const int t = t0 + tt;
                const int par = t & 1;

                const float D = fmaf(Et1, ed1s, tailD);
                const float u = D * beta;            // exp(alpha_c - shift)
                if (sl == 0) u_sm[par][c] = u;
                __syncthreads();

                const float* ub = u_sm[par];
                const float uv0 = ub[3 * sl + 0];
                const float uv1 = ub[3 * sl + 1];
                const float uv2 = ub[3 * sl + 2];

                // Phase-B partial (3 FMA).
                float w = fmaf(uv2, etr2, fmaf(uv1, etr1, uv0 * etr0));

                // Tail for t+1: 13 contiguous LDS (immediate offsets).
                const float* p = ringc + (((t - 1 - 13 * sl) & 127) + 128 - 12);
                float ta = p[12] * edt[0];
                float tb2 = p[11] * edt[1];
                float tc = p[10] * edt[2];
                ta = fmaf(p[9], edt[3], ta);
                tb2 = fmaf(p[8], edt[4], tb2);
                tc = fmaf(p[7], edt[5], tc);
                ta = fmaf(p[6], edt[6], ta);
                tb2 = fmaf(p[5], edt[7], tb2);
                tc = fmaf(p[4], edt[8], tc);
                ta = fmaf(p[3], edt[9], ta);
                tb2 = fmaf(p[2], edt[10], tb2);
                tc = fmaf(p[1], edt[11], tc);
                ta = fmaf(p[0], edt[12], ta);
                float tb = ta + tb2 + tc;

                // 3-round group butterflies, interleaved.
#pragma unroll
                for (int off = 4; off > 0; off >>= 1) {
                    w  += __shfl_xor_sync(FULL, w, off);
                    tb += __shfl_xor_sync(FULL, tb, off);
                }

                const float Et = w * rbeta;          // E[t]
                if (sl == 0) {
                    ringc[t & 127] = Et;
                    ringc[(t & 127) + 128] = Et;
                }

                if (t == len) {
                    float su = uv0 + uv1 + uv2;
#pragma unroll
                    for (int off = 4; off > 0; off >>= 1)
                        su += __shfl_xor_sync(FULL, su, off);
                    if (tid == 0) out[b] = shift + __logf(fmaxf(su, 1e-37f));
                }

                // shift feedback (uniform across warps; pure ALU).
                const float u0 = __shfl_sync(FULL, uv0, 0);
                int e0 = (__float_as_int(u0) >> 23) & 255;
                int ds = (e0 == 0) ? -30 : (e0 - 127);
                ds = ds < -30 ? -30 : (ds > 30 ? 30 : ds);
                shift = fmaf((float)ds, LN2, shift);

                // beta/rbeta for step t+1 (cum[t+1] broadcast within group).
                const float crN = __shfl_sync(FULL, cumA[tt >> 3], laneBase + (tt & 7)) + R;
                const float xn = crN - shift;
                beta = __expf(xn);
                rbeta = __expf(-xn);

                Et1 = Et;
                tailD = tb;
            }
        }
        if (t0 + 31 >= len) break;
#pragma unroll
        for (int m = 0; m < 4; ++m) cumA[m] = cumB[m];
    }
}

// ---------------------------------------------------------------------------
extern "C" void kernel_launch(void* const* d_in, const int* in_sizes, int n_in,
                              void* d_out, int out_size) {
    const float* hs    = (const float*)d_in[0];   // [B,T,H]
    const float* W     = (const float*)d_in[1];   // [H,C]
    const float* bias  = (const float*)d_in[2];   // [C]
    const float* trans = (const float*)d_in[3];   // [C,C]
    const float* dur   = (const float*)d_in[4];   // [K,C]
    const int*   len   = (const int*)d_in[5];     // [B]
    float* out = (float*)d_out;

    gemm_kernel<<<(NB * NT) / 256, 256>>>(hs, W, bias);
    cumsum_kernel<<<NB * NC, 32>>>();
    scan_kernel<<<NB, 192>>>(trans, dur, len, out);
}